// round 1
// baseline (speedup 1.0000x reference)
#include <cuda_runtime.h>
#include <cuda_bf16.h>

// SENet gate kernel: out[b, e] = x[b, e] * sigmoid(MLP(segment_means(x[b,:])))[seg(e)]
//
// Pure HBM-bound: 376 MB in + 376 MB out. Strategy: one 256-thread block
// handles 16 rows. Row tile (16 x 188 f32 = 12 KB) staged in SMEM so x is
// read from DRAM exactly once; tile is a contiguous 752-float4 region of
// global memory, so load/store phases are perfectly coalesced float4 copies.

#define ROWS_PER_BLOCK 16
#define NTHREADS 256
#define NFEAT 188
#define NF4 47            // 188 / 4

__constant__ int   c_bounds[13] = {0,20,26,47,67,73,94,114,120,141,161,167,188};
__constant__ float c_invlen[12] = {
    1.0f/20.f, 1.0f/6.f, 1.0f/21.f,
    1.0f/20.f, 1.0f/6.f, 1.0f/21.f,
    1.0f/20.f, 1.0f/6.f, 1.0f/21.f,
    1.0f/20.f, 1.0f/6.f, 1.0f/21.f
};

__global__ __launch_bounds__(NTHREADS)
void senet_kernel(const float* __restrict__ x,
                  const float* __restrict__ W1,   // [3,12]
                  const float* __restrict__ b1,   // [3]
                  const float* __restrict__ W2,   // [12,3]
                  const float* __restrict__ b2,   // [12]
                  float* __restrict__ out,
                  int B)
{
    __shared__ float sx[ROWS_PER_BLOCK * NFEAT];       // 12032 B
    __shared__ float smeans[ROWS_PER_BLOCK][12];
    __shared__ float sgates[ROWS_PER_BLOCK][12];
    __shared__ float sW1[36];
    __shared__ float sb1[3];
    __shared__ float sW2[36];
    __shared__ float sb2[12];
    __shared__ unsigned char ssid[NFEAT];

    const int tid = threadIdx.x;
    const long long base_row = (long long)blockIdx.x * ROWS_PER_BLOCK;
    const int rows = min(ROWS_PER_BLOCK, B - (int)base_row);
    const int n4 = rows * NF4;

    const float4* __restrict__ gx   = (const float4*)(x   + base_row * NFEAT);
    float4*       __restrict__ gout = (float4*)      (out + base_row * NFEAT);

    // ---- phase 1: coalesced tile load + stage weights + segment-id table ----
    #pragma unroll 3
    for (int i = tid; i < n4; i += NTHREADS)
        ((float4*)sx)[i] = gx[i];

    if (tid < 36) sW1[tid] = W1[tid];
    if (tid < 3)  sb1[tid] = b1[tid];
    if (tid < 36) sW2[tid] = W2[tid];
    if (tid < 12) sb2[tid] = b2[tid];
    if (tid < NFEAT) {
        int s = 0;
        #pragma unroll
        for (int k = 1; k < 12; ++k) s += (tid >= c_bounds[k]);
        ssid[tid] = (unsigned char)s;
    }
    __syncthreads();

    // ---- phase 2: per-(row, segment) means (12 threads per row) ----
    if (tid < rows * 12) {
        const int row = tid / 12;
        const int s   = tid % 12;
        const float* xr = sx + row * NFEAT;
        const int lo = c_bounds[s], hi = c_bounds[s + 1];
        float acc = 0.f;
        for (int c = lo; c < hi; ++c) acc += xr[c];
        smeans[row][s] = acc * c_invlen[s];
    }
    __syncthreads();

    // ---- phase 3: tiny MLP, one thread per row ----
    if (tid < rows) {
        float h[3];
        #pragma unroll
        for (int j = 0; j < 3; ++j) {
            float a = sb1[j];
            #pragma unroll
            for (int k = 0; k < 12; ++k) a += smeans[tid][k] * sW1[j * 12 + k];
            h[j] = fmaxf(a, 0.f);
        }
        #pragma unroll
        for (int s = 0; s < 12; ++s) {
            float a = sb2[s];
            #pragma unroll
            for (int j = 0; j < 3; ++j) a += h[j] * sW2[s * 3 + j];
            sgates[tid][s] = 1.f / (1.f + __expf(-a));
        }
    }
    __syncthreads();

    // ---- phase 4: gate multiply + coalesced store ----
    #pragma unroll 3
    for (int i = tid; i < n4; i += NTHREADS) {
        const int row = i / NF4;
        const int e   = (i % NF4) * 4;
        float4 v = ((float4*)sx)[i];
        v.x *= sgates[row][ssid[e + 0]];
        v.y *= sgates[row][ssid[e + 1]];
        v.z *= sgates[row][ssid[e + 2]];
        v.w *= sgates[row][ssid[e + 3]];
        gout[i] = v;
    }
}

extern "C" void kernel_launch(void* const* d_in, const int* in_sizes, int n_in,
                              void* d_out, int out_size)
{
    const float* x  = (const float*)d_in[0];
    const float* W1 = (const float*)d_in[1];
    const float* b1 = (const float*)d_in[2];
    const float* W2 = (const float*)d_in[3];
    const float* b2 = (const float*)d_in[4];
    float* out = (float*)d_out;

    const int B = in_sizes[0] / NFEAT;
    const int grid = (B + ROWS_PER_BLOCK - 1) / ROWS_PER_BLOCK;
    senet_kernel<<<grid, NTHREADS>>>(x, W1, b1, W2, b2, out, B);
}

// round 2
// speedup vs baseline: 1.9284x; 1.9284x over previous
#include <cuda_runtime.h>
#include <cuda_bf16.h>

// SENet gating, warp-synchronous version.
// Each WARP independently handles 8 rows (8 x 188 f32 = 6016 B tile):
//   1. cp.async.cg (L1-bypass) gmem -> smem, coalesced float4
//   2. segment sums: lane (row=lane/4, quarter=lane&3) sums its contiguous
//      47-float slice (the segment pattern is (20,6,21) x 4) -- perfectly
//      balanced, fully unrolled, provably bank-conflict-free
//   3. MLP 12->3->12 (relu, sigmoid), one lane per row
//   4. gate-multiply from smem + coalesced float4 store
// No __syncthreads anywhere; warps hide each other's DRAM latency.

#define NFEAT 188
#define NF4   47
#define R     8                 // rows per warp
#define WARPS 4
#define NTHREADS (WARPS * 32)   // 128

// packed segment ids for the 4 features of each float4 position (0..46)
__device__ __constant__ unsigned int c_stab[47] = {
    0x00000000u,0x00000000u,0x00000000u,0x00000000u,0x00000000u,
    0x01010101u,0x02020101u,0x02020202u,0x02020202u,0x02020202u,
    0x02020202u,0x03020202u,0x03030303u,0x03030303u,0x03030303u,
    0x03030303u,0x04030303u,0x04040404u,0x05050504u,0x05050505u,
    0x05050505u,0x05050505u,0x05050505u,0x06060505u,0x06060606u,
    0x06060606u,0x06060606u,0x06060606u,0x07070606u,0x07070707u,
    0x08080808u,0x08080808u,0x08080808u,0x08080808u,0x08080808u,
    0x09090908u,0x09090909u,0x09090909u,0x09090909u,0x09090909u,
    0x0A0A0A09u,0x0B0A0A0Au,0x0B0B0B0Bu,0x0B0B0B0Bu,0x0B0B0B0Bu,
    0x0B0B0B0Bu,0x0B0B0B0Bu
};

__global__ __launch_bounds__(NTHREADS, 8)
void senet_kernel(const float* __restrict__ x,
                  const float* __restrict__ W1,   // [3,12]
                  const float* __restrict__ b1,   // [3]
                  const float* __restrict__ W2,   // [12,3]
                  const float* __restrict__ b2,   // [12]
                  float* __restrict__ out,
                  int B)
{
    __shared__ float        sx[WARPS * R * NFEAT];   // 24064 B
    __shared__ float        smeans[WARPS][R][12];
    __shared__ float        sgates[WARPS][R][13];    // pad 13 vs banks
    __shared__ unsigned int sstab[47];

    const int lane = threadIdx.x & 31;
    const int w    = threadIdx.x >> 5;

    const long long row0 = (long long)blockIdx.x * (WARPS * R) + w * R;
    int rows = B - (int)row0;
    if (rows <= 0) return;                  // warp-uniform
    if (rows > R) rows = R;
    const int n4 = rows * NF4;

    float*        sxw  = sx + w * (R * NFEAT);
    const float4* gx   = (const float4*)(x   + row0 * NFEAT);
    float4*       gout = (float4*)      (out + row0 * NFEAT);

    // sid table -> smem (all warps write identical values; benign)
    for (int j = lane; j < 47; j += 32) sstab[j] = c_stab[j];

    // ---- phase 1: async, L1-bypassing tile load ----
    unsigned int sbase = (unsigned int)__cvta_generic_to_shared(sxw);
    for (int i = lane; i < n4; i += 32) {
        asm volatile("cp.async.cg.shared.global [%0], [%1], 16;\n"
                     :: "r"(sbase + i * 16), "l"(gx + i) : "memory");
    }
    asm volatile("cp.async.commit_group;\n" ::: "memory");
    asm volatile("cp.async.wait_group 0;\n" ::: "memory");
    __syncwarp();

    // ---- phase 2: segment sums (balanced, conflict-free) ----
    {
        const int rq = lane >> 2;           // row within warp tile
        const int sq = lane & 3;            // quarter (3 segments each)
        if (rq < rows) {
            const float* xr = sxw + rq * NFEAT + sq * 47;
            float a0 = 0.f, a1 = 0.f, a2 = 0.f;
            #pragma unroll
            for (int j = 0;  j < 20; ++j) a0 += xr[j];
            #pragma unroll
            for (int j = 20; j < 26; ++j) a1 += xr[j];
            #pragma unroll
            for (int j = 26; j < 47; ++j) a2 += xr[j];
            smeans[w][rq][3 * sq + 0] = a0 * (1.f / 20.f);
            smeans[w][rq][3 * sq + 1] = a1 * (1.f / 6.f);
            smeans[w][rq][3 * sq + 2] = a2 * (1.f / 21.f);
        }
    }
    __syncwarp();

    // ---- phase 3: tiny MLP, one lane per row ----
    if (lane < rows) {
        float m[12];
        #pragma unroll
        for (int k = 0; k < 12; ++k) m[k] = smeans[w][lane][k];
        float h[3];
        #pragma unroll
        for (int j = 0; j < 3; ++j) {
            float a = __ldg(b1 + j);
            #pragma unroll
            for (int k = 0; k < 12; ++k) a += m[k] * __ldg(W1 + j * 12 + k);
            h[j] = fmaxf(a, 0.f);
        }
        #pragma unroll
        for (int s = 0; s < 12; ++s) {
            float a = __ldg(b2 + s);
            #pragma unroll
            for (int j = 0; j < 3; ++j) a += h[j] * __ldg(W2 + s * 3 + j);
            sgates[w][lane][s] = __fdividef(1.f, 1.f + __expf(-a));
        }
    }
    __syncwarp();

    // ---- phase 4: gate multiply + coalesced store ----
    const float4* sxw4 = (const float4*)sxw;
    for (int i = lane; i < n4; i += 32) {
        const int row = i / NF4;
        const int p   = i - row * NF4;
        const unsigned int sid = sstab[p];
        const float* gr = sgates[w][row];
        float4 v = sxw4[i];
        v.x *= gr[sid         & 255];
        v.y *= gr[(sid >> 8)  & 255];
        v.z *= gr[(sid >> 16) & 255];
        v.w *= gr[ sid >> 24       ];
        gout[i] = v;
    }
}

extern "C" void kernel_launch(void* const* d_in, const int* in_sizes, int n_in,
                              void* d_out, int out_size)
{
    const float* x  = (const float*)d_in[0];
    const float* W1 = (const float*)d_in[1];
    const float* b1 = (const float*)d_in[2];
    const float* W2 = (const float*)d_in[3];
    const float* b2 = (const float*)d_in[4];
    float* out = (float*)d_out;

    const int B = in_sizes[0] / NFEAT;
    const int rows_per_block = WARPS * R;   // 32
    const int grid = (B + rows_per_block - 1) / rows_per_block;
    senet_kernel<<<grid, NTHREADS>>>(x, W1, b1, W2, b2, out, B);
}